// round 1
// baseline (speedup 1.0000x reference)
#include <cuda_runtime.h>
#include <math.h>

#define T_TOK 8192
#define DIM   2048
#define ODIM  2048
#define NE    8

// ---------------- device scratch (static, no allocations) ----------------
__device__ float g_Wfull[(size_t)NE * DIM * ODIM];   // 128 MB dense PHM weights
__device__ int   g_gate[T_TOK];
__device__ float g_tprob[T_TOK];
__device__ float g_Psum[NE];
__device__ int   g_count[NE];
__device__ int   g_fill[NE];
__device__ int   g_off[NE];
__device__ int   g_perm[T_TOK];
__device__ int   g_tile_e[80];
__device__ int   g_tile_r0[80];
__device__ int   g_tile_nv[80];
__device__ int   g_numtiles;

// ---------------- reset accumulators (graph replays!) ----------------
__global__ void zero_k() {
    int i = threadIdx.x;
    if (i < NE) { g_Psum[i] = 0.f; g_count[i] = 0; g_fill[i] = 0; }
}

// ---------------- gating: one warp per token ----------------
__global__ void gate_k(const float* __restrict__ x, const float* __restrict__ gw) {
    __shared__ float sP[NE];
    __shared__ int   sC[NE];
    if (threadIdx.x < NE) { sP[threadIdx.x] = 0.f; sC[threadIdx.x] = 0; }
    __syncthreads();

    int warp = threadIdx.x >> 5, lane = threadIdx.x & 31;
    int t = blockIdx.x * 8 + warp;
    const float*  xr = x + (size_t)t * DIM;
    const float4* g4 = (const float4*)gw;

    float acc[8] = {0.f,0.f,0.f,0.f,0.f,0.f,0.f,0.f};
    for (int d = lane; d < DIM; d += 32) {
        float xv = xr[d];
        float4 a = g4[d * 2];
        float4 b = g4[d * 2 + 1];
        acc[0] += xv * a.x; acc[1] += xv * a.y; acc[2] += xv * a.z; acc[3] += xv * a.w;
        acc[4] += xv * b.x; acc[5] += xv * b.y; acc[6] += xv * b.z; acc[7] += xv * b.w;
    }
#pragma unroll
    for (int e = 0; e < 8; e++)
#pragma unroll
        for (int off = 16; off; off >>= 1)
            acc[e] += __shfl_down_sync(0xffffffffu, acc[e], off);

    if (lane == 0) {
        float m = acc[0]; int best = 0;
        for (int e = 1; e < 8; e++) if (acc[e] > m) { m = acc[e]; best = e; }  // first-max like jnp.argmax
        float p[8], s = 0.f;
        for (int e = 0; e < 8; e++) { p[e] = expf(acc[e] - m); s += p[e]; }
        float inv = 1.f / s;
        g_gate[t]  = best;
        g_tprob[t] = p[best] * inv;
        for (int e = 0; e < 8; e++) atomicAdd(&sP[e], p[e] * inv);
        atomicAdd(&sC[best], 1);
    }
    __syncthreads();
    if (threadIdx.x < NE) {
        atomicAdd(&g_Psum[threadIdx.x], sP[threadIdx.x]);
        atomicAdd(&g_count[threadIdx.x], sC[threadIdx.x]);
    }
}

// ---------------- offsets + tile table (single thread) ----------------
__global__ void prep_k() {
    if (threadIdx.x | blockIdx.x) return;
    int off = 0, nt = 0;
    for (int e = 0; e < NE; e++) {
        int c = g_count[e];
        g_off[e] = off;
        for (int r = 0; r < c; r += 128) {
            g_tile_e[nt]  = e;
            g_tile_r0[nt] = off + r;
            g_tile_nv[nt] = min(128, c - r);
            nt++;
        }
        off += c;
    }
    g_numtiles = nt;
}

// ---------------- scatter tokens into per-expert buckets ----------------
__global__ void scatter_k() {
    int t = blockIdx.x * blockDim.x + threadIdx.x;
    if (t >= T_TOK) return;
    int e = g_gate[t];
    int pos = g_off[e] + atomicAdd(&g_fill[e], 1);
    g_perm[pos] = t;
}

// ---------------- densify PHM weights: Wfull[e] = sum_p kron(rule[e,p], W[e,p]) ----
__global__ void wfull_k(const float* __restrict__ rule, const float* __restrict__ W) {
    size_t idx = (size_t)blockIdx.x * blockDim.x + threadIdx.x;   // < 8*2048*512 (float4 granules)
    int oq = (int)(idx & 511);
    int d  = (int)((idx >> 9) & (DIM - 1));
    int e  = (int)(idx >> 20);
    int a = d >> 9, i = d & 511;
    int o0 = oq << 2;
    int bq = o0 >> 9, j = o0 & 511;
    float4 acc = make_float4(0.f, 0.f, 0.f, 0.f);
#pragma unroll
    for (int p = 0; p < 4; p++) {
        float r = rule[((e * 4 + p) * 4 + a) * 4 + bq];
        const float4 wv = *(const float4*)(W + ((size_t)((e * 4 + p) * 512 + i) * 512 + j));
        acc.x += r * wv.x; acc.y += r * wv.y; acc.z += r * wv.z; acc.w += r * wv.w;
    }
    *(float4*)(g_Wfull + (idx << 2)) = acc;
}

// ---------------- grouped GEMM: 128x128x8 tiles, 8x8 microtiles ----------------
__global__ __launch_bounds__(256) void gemm_k(const float* __restrict__ x,
                                              const float* __restrict__ bias,
                                              float* __restrict__ out) {
    int tile = blockIdx.x;
    if (tile >= g_numtiles) return;

    __shared__ float As[8][128];
    __shared__ float Bs[8][128];
    __shared__ int   sTok[128];
    __shared__ float sPr[128];

    int e  = g_tile_e[tile];
    int r0 = g_tile_r0[tile];
    int nv = g_tile_nv[tile];
    int colBase = blockIdx.y * 128;
    int tid = threadIdx.x;

    if (tid < 128) {
        int t = (tid < nv) ? g_perm[r0 + tid] : 0;
        sTok[tid] = t;
        sPr[tid]  = g_tprob[t];
    }
    __syncthreads();

    const float* Bbase = g_Wfull + (size_t)e * DIM * ODIM + colBase;

    int arow = tid >> 1, kq = tid & 1;
    const float* Aptr = x + (size_t)sTok[arow] * DIM + kq * 4;
    int brow = tid >> 5, bc = (tid & 31) << 2;
    const float* Bptr = Bbase + (size_t)brow * ODIM + bc;

    int tx = tid & 15, ty = tid >> 4;

    float acc[8][8];
#pragma unroll
    for (int i = 0; i < 8; i++)
#pragma unroll
        for (int j = 0; j < 8; j++) acc[i][j] = 0.f;

    for (int k0 = 0; k0 < DIM; k0 += 8) {
        float4 av = *(const float4*)(Aptr + k0);
        float4 bv = *(const float4*)(Bptr + (size_t)k0 * ODIM);
        __syncthreads();
        As[kq * 4 + 0][arow] = av.x;
        As[kq * 4 + 1][arow] = av.y;
        As[kq * 4 + 2][arow] = av.z;
        As[kq * 4 + 3][arow] = av.w;
        *(float4*)&Bs[brow][bc] = bv;
        __syncthreads();
#pragma unroll
        for (int k = 0; k < 8; k++) {
            float a[8], b[8];
#pragma unroll
            for (int i = 0; i < 4; i++) {
                a[i]     = As[k][ty * 4 + i];
                a[4 + i] = As[k][64 + ty * 4 + i];
                b[i]     = Bs[k][tx * 4 + i];
                b[4 + i] = Bs[k][64 + tx * 4 + i];
            }
#pragma unroll
            for (int i = 0; i < 8; i++)
#pragma unroll
                for (int j = 0; j < 8; j++) acc[i][j] += a[i] * b[j];
        }
    }

    // epilogue: scatter rows back to token order, scale by gate prob, add bias
#pragma unroll
    for (int hr = 0; hr < 2; hr++)
#pragma unroll
        for (int i = 0; i < 4; i++) {
            int rl = hr * 64 + ty * 4 + i;
            if (rl < nv) {
                int t = sTok[rl];
                float sc = sPr[rl];
#pragma unroll
                for (int hc = 0; hc < 2; hc++) {
                    int c = colBase + hc * 64 + tx * 4;
                    float4 bf = *(const float4*)(bias + e * ODIM + c);
                    float4 o;
                    o.x = (acc[hr * 4 + i][hc * 4 + 0] + bf.x) * sc;
                    o.y = (acc[hr * 4 + i][hc * 4 + 1] + bf.y) * sc;
                    o.z = (acc[hr * 4 + i][hc * 4 + 2] + bf.z) * sc;
                    o.w = (acc[hr * 4 + i][hc * 4 + 3] + bf.w) * sc;
                    *(float4*)(out + (size_t)t * ODIM + c) = o;
                }
            }
        }
}

// ---------------- balance loss + num_tokens tail ----------------
__global__ void fin_k(float* __restrict__ out) {
    if (threadIdx.x | blockIdx.x) return;
    float tot = 0.f;
    for (int e = 0; e < NE; e++)
        tot += (g_Psum[e] / (float)T_TOK) * ((float)g_count[e] / (float)T_TOK);
    out[(size_t)T_TOK * ODIM] = (float)NE * tot;
    for (int e = 0; e < NE; e++)
        out[(size_t)T_TOK * ODIM + 1 + e] = (float)g_count[e];
}

extern "C" void kernel_launch(void* const* d_in, const int* in_sizes, int n_in,
                              void* d_out, int out_size) {
    const float* x    = (const float*)d_in[0];   // hidden_states [4,2048,2048]
    const float* gw   = (const float*)d_in[1];   // gate_w [2048,8]
    const float* rule = (const float*)d_in[2];   // phm_rule [8,4,4,4]
    const float* W    = (const float*)d_in[3];   // W [8,4,512,512]
    const float* bias = (const float*)d_in[4];   // b [8,2048]
    float* out = (float*)d_out;

    zero_k<<<1, 32>>>();
    wfull_k<<<32768, 256>>>(rule, W);            // independent of gating
    gate_k<<<1024, 256>>>(x, gw);
    prep_k<<<1, 1>>>();
    scatter_k<<<32, 256>>>();
    dim3 grid(72, 16);                           // max row-tiles = 71, 16 col-tiles
    gemm_k<<<grid, 256>>>(x, bias, out);
    fin_k<<<1, 1>>>(out);
}

// round 3
// speedup vs baseline: 5.3375x; 5.3375x over previous
#include <cuda_runtime.h>
#include <cuda_fp16.h>
#include <math.h>
#include <stdint.h>

#define T_TOK 8192
#define DIM   2048
#define ODIM  2048
#define NE    8
#define BM    128
#define BN    128
#define BK    64            // halves per K stage chunk (= 128 B per row)
#define NC    (DIM / BK)    // 32 chunks
#define STAGE_BYTES (BM * 128 + BN * 128)   // 16KB A + 16KB B
#define SMEM_SZ (1024 + 4 * STAGE_BYTES)

// ---------------- device scratch ----------------
__device__ __half g_WfullT[(size_t)NE * ODIM * DIM];  // [e][o][d] fp16 (B operand, k contiguous)
__device__ __half g_Xperm[(size_t)T_TOK * DIM];       // permuted tokens fp16 (A operand)
__device__ int    g_gate[T_TOK];
__device__ float  g_tprob[T_TOK];
__device__ float  g_Psum[NE];
__device__ int    g_count[NE], g_fill[NE], g_off[NE];
__device__ int    g_perm[T_TOK];
__device__ int    g_tile_e[80], g_tile_r0[80], g_tile_nv[80];
__device__ int    g_numtiles;

// ---------------- PTX helpers ----------------
__device__ __forceinline__ uint32_t smem_u32(const void* p) {
    uint32_t a;
    asm("{ .reg .u64 t; cvta.to.shared.u64 t, %1; cvt.u32.u64 %0, t; }" : "=r"(a) : "l"(p));
    return a;
}
#define SW128(off) ((off) ^ (((off) >> 3) & 0x70))
#define CP_ASYNC16(dst, src) \
    asm volatile("cp.async.cg.shared.global [%0], [%1], 16;" :: "r"(dst), "l"(src))
#define CP_COMMIT() asm volatile("cp.async.commit_group;")
#define CP_WAIT2()  asm volatile("cp.async.wait_group 2;")

__device__ __forceinline__ void ldsm_x4(uint32_t* r, uint32_t addr) {
    asm volatile("ldmatrix.sync.aligned.m8n8.x4.shared.b16 {%0,%1,%2,%3}, [%4];"
                 : "=r"(r[0]), "=r"(r[1]), "=r"(r[2]), "=r"(r[3]) : "r"(addr));
}
__device__ __forceinline__ void mma16816(float* d, const uint32_t* a, uint32_t b0, uint32_t b1) {
    asm volatile("mma.sync.aligned.m16n8k16.row.col.f32.f16.f16.f32 "
                 "{%0,%1,%2,%3},{%4,%5,%6,%7},{%8,%9},{%0,%1,%2,%3};"
                 : "+f"(d[0]), "+f"(d[1]), "+f"(d[2]), "+f"(d[3])
                 : "r"(a[0]), "r"(a[1]), "r"(a[2]), "r"(a[3]), "r"(b0), "r"(b1));
}

// ---------------- reset accumulators ----------------
__global__ void zero_k() {
    int i = threadIdx.x;
    if (i < NE) { g_Psum[i] = 0.f; g_count[i] = 0; g_fill[i] = 0; }
}

// ---------------- gating: one warp per token (identical to R1 for argmax stability) ----
__global__ void gate_k(const float* __restrict__ x, const float* __restrict__ gw) {
    __shared__ float sP[NE];
    __shared__ int   sC[NE];
    if (threadIdx.x < NE) { sP[threadIdx.x] = 0.f; sC[threadIdx.x] = 0; }
    __syncthreads();
    int warp = threadIdx.x >> 5, lane = threadIdx.x & 31;
    int t = blockIdx.x * 8 + warp;
    const float*  xr = x + (size_t)t * DIM;
    const float4* g4 = (const float4*)gw;
    float acc[8] = {0.f,0.f,0.f,0.f,0.f,0.f,0.f,0.f};
    for (int d = lane; d < DIM; d += 32) {
        float xv = xr[d];
        float4 a = g4[d * 2];
        float4 b = g4[d * 2 + 1];
        acc[0] += xv * a.x; acc[1] += xv * a.y; acc[2] += xv * a.z; acc[3] += xv * a.w;
        acc[4] += xv * b.x; acc[5] += xv * b.y; acc[6] += xv * b.z; acc[7] += xv * b.w;
    }
#pragma unroll
    for (int e = 0; e < 8; e++)
#pragma unroll
        for (int off = 16; off; off >>= 1)
            acc[e] += __shfl_down_sync(0xffffffffu, acc[e], off);
    if (lane == 0) {
        float m = acc[0]; int best = 0;
        for (int e = 1; e < 8; e++) if (acc[e] > m) { m = acc[e]; best = e; }
        float p[8], s = 0.f;
        for (int e = 0; e < 8; e++) { p[e] = expf(acc[e] - m); s += p[e]; }
        float inv = 1.f / s;
        g_gate[t]  = best;
        g_tprob[t] = p[best] * inv;
        for (int e = 0; e < 8; e++) atomicAdd(&sP[e], p[e] * inv);
        atomicAdd(&sC[best], 1);
    }
    __syncthreads();
    if (threadIdx.x < NE) {
        atomicAdd(&g_Psum[threadIdx.x], sP[threadIdx.x]);
        atomicAdd(&g_count[threadIdx.x], sC[threadIdx.x]);
    }
}

// ---------------- offsets + tile table ----------------
__global__ void prep_k() {
    if (threadIdx.x | blockIdx.x) return;
    int off = 0, nt = 0;
    for (int e = 0; e < NE; e++) {
        int c = g_count[e];
        g_off[e] = off;
        for (int r = 0; r < c; r += BM) {
            g_tile_e[nt] = e; g_tile_r0[nt] = off + r; g_tile_nv[nt] = min(BM, c - r); nt++;
        }
        off += c;
    }
    g_numtiles = nt;
}

// ---------------- bucket scatter ----------------
__global__ void scatter_k() {
    int t = blockIdx.x * blockDim.x + threadIdx.x;
    if (t >= T_TOK) return;
    int e = g_gate[t];
    int pos = g_off[e] + atomicAdd(&g_fill[e], 1);
    g_perm[pos] = t;
}

// ---------------- gather permuted tokens -> fp16 ----------------
__global__ void permute_k(const float* __restrict__ x) {
    int r = blockIdx.x;
    int c0 = threadIdx.x * 8;
    int t = __ldg(&g_perm[r]);
    const float4* s = (const float4*)(x + (size_t)t * DIM + c0);
    float4 v0 = s[0], v1 = s[1];
    __half2 h[4];
    h[0] = __float22half2_rn(make_float2(v0.x, v0.y));
    h[1] = __float22half2_rn(make_float2(v0.z, v0.w));
    h[2] = __float22half2_rn(make_float2(v1.x, v1.y));
    h[3] = __float22half2_rn(make_float2(v1.z, v1.w));
    *(uint4*)(g_Xperm + (size_t)r * DIM + c0) = *(uint4*)h;
}

// ---------------- PHM densify + transpose -> fp16: WfullT[e][o][d] ----------------
__global__ void wfullT_k(const float* __restrict__ rule, const float* __restrict__ W) {
    __shared__ float Cs[32][33];
    int bid = blockIdx.x;
    int e  = bid >> 12;
    int a  = (bid >> 10) & 3;
    int b  = (bid >> 8) & 3;
    int ti = (bid >> 4) & 15;
    int tj = bid & 15;
    float r[4];
#pragma unroll
    for (int p = 0; p < 4; p++) r[p] = rule[((e * 4 + p) * 4 + a) * 4 + b];
    int ii = threadIdx.x >> 3;
    int jq = (threadIdx.x & 7) << 2;
    float4 acc = make_float4(0.f, 0.f, 0.f, 0.f);
#pragma unroll
    for (int p = 0; p < 4; p++) {
        const float4 w = *(const float4*)(W + ((size_t)((e * 4 + p) * 512 + ti * 32 + ii) * 512 + tj * 32 + jq));
        acc.x += r[p] * w.x; acc.y += r[p] * w.y; acc.z += r[p] * w.z; acc.w += r[p] * w.w;
    }
    Cs[ii][jq + 0] = acc.x; Cs[ii][jq + 1] = acc.y; Cs[ii][jq + 2] = acc.z; Cs[ii][jq + 3] = acc.w;
    __syncthreads();
    int jj = ii, iq = jq;
    __half2 o0 = __float22half2_rn(make_float2(Cs[iq + 0][jj], Cs[iq + 1][jj]));
    __half2 o1 = __float22half2_rn(make_float2(Cs[iq + 2][jj], Cs[iq + 3][jj]));
    size_t o = (size_t)e * ODIM + b * 512 + tj * 32 + jj;
    __half* dst = g_WfullT + o * DIM + a * 512 + ti * 32 + iq;
    *(__half2*)(dst)     = o0;
    *(__half2*)(dst + 2) = o1;
}

// ---------------- HMMA fp16 grouped GEMM: 128x128x64 tiles, 4-stage cp.async ----------------
__global__ __launch_bounds__(256) void gemm_k(const float* __restrict__ bias,
                                              float* __restrict__ out) {
    extern __shared__ char smem[];
    int tile = blockIdx.x;
    if (tile >= g_numtiles) return;

    int*   sTok = (int*)smem;            // 128 ints
    float* sPr  = (float*)(smem + 512);  // 128 floats
    uint32_t sbu = smem_u32(smem);

    int e = g_tile_e[tile], r0 = g_tile_r0[tile], nv = g_tile_nv[tile];
    int colBase = blockIdx.y * BN;
    int tid = threadIdx.x, wid = tid >> 5, lane = tid & 31;
    int warp_m = wid >> 2, warp_n = wid & 3;

    if (tid < BM) {
        int t = g_perm[r0 + tid];
        sTok[tid] = t;
        sPr[tid]  = g_tprob[t];
    }
    __syncthreads();

    const __half* Abase = g_Xperm  + (size_t)r0 * DIM;
    const __half* Bbase = g_WfullT + ((size_t)e * ODIM + colBase) * DIM;

    auto load_chunk = [&](int c) {
        int s = c & 3;
        uint32_t sa = sbu + 1024 + s * STAGE_BYTES;
        uint32_t sb = sa + BM * 128;
        const __half* ga = Abase + c * BK;
        const __half* gb = Bbase + c * BK;
#pragma unroll
        for (int i = 0; i < 4; i++) {                 // A: 1024 units / 256 thr = 4
            int u = tid + i * 256;
            int row = u >> 3, sub = u & 7;
            CP_ASYNC16(sa + SW128(row * 128 + sub * 16), ga + (size_t)row * DIM + sub * 8);
        }
#pragma unroll
        for (int i = 0; i < 4; i++) {                 // B: 1024 units
            int u = tid + i * 256;
            int row = u >> 3, sub = u & 7;
            CP_ASYNC16(sb + SW128(row * 128 + sub * 16), gb + (size_t)row * DIM + sub * 8);
        }
    };

    float acc[4][4][4];
#pragma unroll
    for (int i = 0; i < 4; i++)
#pragma unroll
        for (int j = 0; j < 4; j++)
#pragma unroll
            for (int k = 0; k < 4; k++) acc[i][j][k] = 0.f;

    // ldmatrix per-lane geometry
    int q = lane >> 3, r = lane & 7;
    int mA  = warp_m * 64 + r + ((q & 1) << 3);   // A row for this lane
    int kqa = (q >> 1) << 4;                      // A k byte offset within step
    int nB  = warp_n * 32 + r + ((q >> 1) << 3);  // B row (n) for this lane
    int kqb = (q & 1) << 4;                       // B k byte offset within step

    // prologue
    load_chunk(0); CP_COMMIT();
    load_chunk(1); CP_COMMIT();
    load_chunk(2); CP_COMMIT();

    for (int c = 0; c < NC; c++) {
        CP_WAIT2();
        __syncthreads();
        if (c + 3 < NC) load_chunk(c + 3);
        CP_COMMIT();

        uint32_t sa = sbu + 1024 + (c & 3) * STAGE_BYTES;
        uint32_t sb = sa + BM * 128;
#pragma unroll
        for (int step = 0; step < 4; step++) {
            uint32_t a[4][4];
#pragma unroll
            for (int mt = 0; mt < 4; mt++)
                ldsm_x4(a[mt], sa + SW128((mA + mt * 16) * 128 + step * 32 + kqa));
            uint32_t bf[2][4];
#pragma unroll
            for (int np = 0; np < 2; np++)
                ldsm_x4(bf[np], sb + SW128((nB + np * 16) * 128 + step * 32 + kqb));
#pragma unroll
            for (int mt = 0; mt < 4; mt++)
#pragma unroll
                for (int nt = 0; nt < 4; nt++)
                    mma16816(acc[mt][nt], a[mt],
                             bf[nt >> 1][(nt & 1) << 1], bf[nt >> 1][((nt & 1) << 1) + 1]);
        }
    }

    // epilogue: scatter to token rows, add bias, scale by gate prob
    int rowq = lane >> 2, colq = (lane & 3) << 1;
#pragma unroll
    for (int mt = 0; mt < 4; mt++) {
#pragma unroll
        for (int half = 0; half < 2; half++) {
            int rl = warp_m * 64 + mt * 16 + rowq + half * 8;
            if (rl < nv) {
                int t = sTok[rl];
                float pr = sPr[rl];
                float* op = out + (size_t)t * ODIM + colBase;
                const float* bp = bias + e * ODIM + colBase;
#pragma unroll
                for (int nt = 0; nt < 4; nt++) {
                    int col = warp_n * 32 + nt * 8 + colq;
                    float2 b2 = *(const float2*)(bp + col);
                    float2 o;
                    o.x = (acc[mt][nt][half * 2 + 0] + b2.x) * pr;
                    o.y = (acc[mt][nt][half * 2 + 1] + b2.y) * pr;
                    *(float2*)(op + col) = o;
                }
            }
        }
    }
}

// ---------------- balance loss + num_tokens ----------------
__global__ void fin_k(float* __restrict__ out) {
    if (threadIdx.x | blockIdx.x) return;
    float tot = 0.f;
    for (int e = 0; e < NE; e++)
        tot += (g_Psum[e] / (float)T_TOK) * ((float)g_count[e] / (float)T_TOK);
    out[(size_t)T_TOK * ODIM] = (float)NE * tot;
    for (int e = 0; e < NE; e++)
        out[(size_t)T_TOK * ODIM + 1 + e] = (float)g_count[e];
}

extern "C" void kernel_launch(void* const* d_in, const int* in_sizes, int n_in,
                              void* d_out, int out_size) {
    const float* x    = (const float*)d_in[0];
    const float* gw   = (const float*)d_in[1];
    const float* rule = (const float*)d_in[2];
    const float* W    = (const float*)d_in[3];
    const float* bias = (const float*)d_in[4];
    float* out = (float*)d_out;

    cudaFuncSetAttribute(gemm_k, cudaFuncAttributeMaxDynamicSharedMemorySize, SMEM_SZ);

    zero_k<<<1, 32>>>();
    gate_k<<<1024, 256>>>(x, gw);
    prep_k<<<1, 1>>>();
    scatter_k<<<32, 256>>>();
    permute_k<<<T_TOK, 256>>>(x);
    wfullT_k<<<32768, 256>>>(rule, W);
    dim3 grid(72, ODIM / BN);
    gemm_k<<<grid, 256, SMEM_SZ>>>(bias, out);
    fin_k<<<1, 1>>>(out);
}

// round 4
// speedup vs baseline: 5.4094x; 1.0135x over previous
#include <cuda_runtime.h>
#include <cuda_fp16.h>
#include <math.h>
#include <stdint.h>

#define T_TOK 8192
#define DIM   2048
#define ODIM  2048
#define NE    8
#define BM    128
#define BN    256
#define BK    64            // halves per K chunk (128 B per row)
#define NC    (DIM / BK)    // 32 chunks
#define STAGE_BYTES ((BM + BN) * 128)       // 48KB
#define SMEM_SZ (1024 + 3 * STAGE_BYTES)    // 145KB

// ---------------- device scratch ----------------
__device__ __half g_WfullT[(size_t)NE * ODIM * DIM];  // [e][o][d] fp16, k contiguous
__device__ __half g_Xperm[(size_t)T_TOK * DIM];       // permuted tokens fp16
__device__ int    g_gate[T_TOK];
__device__ float  g_tprob[T_TOK];
__device__ float  g_Psum[NE];
__device__ int    g_count[NE], g_fill[NE], g_off[NE];
__device__ int    g_perm[T_TOK];
__device__ int    g_tile_e[80], g_tile_r0[80], g_tile_nv[80];
__device__ int    g_numtiles;

// ---------------- PTX helpers ----------------
__device__ __forceinline__ uint32_t smem_u32(const void* p) {
    uint32_t a;
    asm("{ .reg .u64 t; cvta.to.shared.u64 t, %1; cvt.u32.u64 %0, t; }" : "=r"(a) : "l"(p));
    return a;
}
#define SW128(off) ((off) ^ (((off) >> 3) & 0x70))
#define CP_ASYNC16(dst, src) \
    asm volatile("cp.async.cg.shared.global [%0], [%1], 16;" :: "r"(dst), "l"(src))
#define CP_COMMIT() asm volatile("cp.async.commit_group;")
#define CP_WAIT1()  asm volatile("cp.async.wait_group 1;")

__device__ __forceinline__ void ldsm_x4(uint32_t* r, uint32_t addr) {
    asm volatile("ldmatrix.sync.aligned.m8n8.x4.shared.b16 {%0,%1,%2,%3}, [%4];"
                 : "=r"(r[0]), "=r"(r[1]), "=r"(r[2]), "=r"(r[3]) : "r"(addr));
}
__device__ __forceinline__ void mma16816(float* d, const uint32_t* a, uint32_t b0, uint32_t b1) {
    asm volatile("mma.sync.aligned.m16n8k16.row.col.f32.f16.f16.f32 "
                 "{%0,%1,%2,%3},{%4,%5,%6,%7},{%8,%9},{%0,%1,%2,%3};"
                 : "+f"(d[0]), "+f"(d[1]), "+f"(d[2]), "+f"(d[3])
                 : "r"(a[0]), "r"(a[1]), "r"(a[2]), "r"(a[3]), "r"(b0), "r"(b1));
}

// ---------------- reset accumulators ----------------
__global__ void zero_k() {
    int i = threadIdx.x;
    if (i < NE) { g_Psum[i] = 0.f; g_count[i] = 0; g_fill[i] = 0; }
}

// ---------------- gating: one warp per token ----------------
__global__ void gate_k(const float* __restrict__ x, const float* __restrict__ gw) {
    __shared__ float sP[NE];
    __shared__ int   sC[NE];
    if (threadIdx.x < NE) { sP[threadIdx.x] = 0.f; sC[threadIdx.x] = 0; }
    __syncthreads();
    int warp = threadIdx.x >> 5, lane = threadIdx.x & 31;
    int t = blockIdx.x * 8 + warp;
    const float*  xr = x + (size_t)t * DIM;
    const float4* g4 = (const float4*)gw;
    float acc[8] = {0.f,0.f,0.f,0.f,0.f,0.f,0.f,0.f};
    for (int d = lane; d < DIM; d += 32) {
        float xv = xr[d];
        float4 a = g4[d * 2];
        float4 b = g4[d * 2 + 1];
        acc[0] += xv * a.x; acc[1] += xv * a.y; acc[2] += xv * a.z; acc[3] += xv * a.w;
        acc[4] += xv * b.x; acc[5] += xv * b.y; acc[6] += xv * b.z; acc[7] += xv * b.w;
    }
#pragma unroll
    for (int e = 0; e < 8; e++)
#pragma unroll
        for (int off = 16; off; off >>= 1)
            acc[e] += __shfl_down_sync(0xffffffffu, acc[e], off);
    if (lane == 0) {
        float m = acc[0]; int best = 0;
        for (int e = 1; e < 8; e++) if (acc[e] > m) { m = acc[e]; best = e; }
        float p[8], s = 0.f;
        for (int e = 0; e < 8; e++) { p[e] = expf(acc[e] - m); s += p[e]; }
        float inv = 1.f / s;
        g_gate[t]  = best;
        g_tprob[t] = p[best] * inv;
        for (int e = 0; e < 8; e++) atomicAdd(&sP[e], p[e] * inv);
        atomicAdd(&sC[best], 1);
    }
    __syncthreads();
    if (threadIdx.x < NE) {
        atomicAdd(&g_Psum[threadIdx.x], sP[threadIdx.x]);
        atomicAdd(&g_count[threadIdx.x], sC[threadIdx.x]);
    }
}

// ---------------- offsets + tiles + scatter + loss tail (one block) ----------------
__global__ void prep_scatter_k(float* __restrict__ out) {
    int tid = threadIdx.x;
    if (tid == 0) {
        int off = 0, nt = 0;
        for (int e = 0; e < NE; e++) {
            int c = g_count[e];
            g_off[e] = off;
            for (int r = 0; r < c; r += BM) {
                g_tile_e[nt] = e; g_tile_r0[nt] = off + r; g_tile_nv[nt] = min(BM, c - r); nt++;
            }
            off += c;
        }
        g_numtiles = nt;
        // loss + counts tail
        float tot = 0.f;
        for (int e = 0; e < NE; e++)
            tot += (g_Psum[e] / (float)T_TOK) * ((float)g_count[e] / (float)T_TOK);
        out[(size_t)T_TOK * ODIM] = (float)NE * tot;
        for (int e = 0; e < NE; e++)
            out[(size_t)T_TOK * ODIM + 1 + e] = (float)g_count[e];
    }
    __syncthreads();
    for (int t = tid; t < T_TOK; t += blockDim.x) {
        int e = g_gate[t];
        int pos = g_off[e] + atomicAdd(&g_fill[e], 1);
        g_perm[pos] = t;
    }
}

// ---------------- gather permuted tokens -> fp16 ----------------
__global__ void permute_k(const float* __restrict__ x) {
    int r = blockIdx.x;
    int c0 = threadIdx.x * 8;
    int t = __ldg(&g_perm[r]);
    const float4* s = (const float4*)(x + (size_t)t * DIM + c0);
    float4 v0 = s[0], v1 = s[1];
    __half2 h[4];
    h[0] = __float22half2_rn(make_float2(v0.x, v0.y));
    h[1] = __float22half2_rn(make_float2(v0.z, v0.w));
    h[2] = __float22half2_rn(make_float2(v1.x, v1.y));
    h[3] = __float22half2_rn(make_float2(v1.z, v1.w));
    *(uint4*)(g_Xperm + (size_t)r * DIM + c0) = *(uint4*)h;
}

// ---------------- PHM densify + transpose -> fp16 (W read once) ----------------
// block = (e, ti, tj): loads 4 W tiles (p=0..3) of 32x32 transposed into smem,
// then emits all 16 (a,b) kron cells.
__global__ __launch_bounds__(256) void wfullT_k(const float* __restrict__ rule,
                                                const float* __restrict__ W) {
    __shared__ float Ws[4][32][33];   // [p][j][i] transposed
    int bid = blockIdx.x;
    int e  = bid >> 8;
    int ti = (bid >> 4) & 15;
    int tj = bid & 15;
    int tid = threadIdx.x;
    int ii = tid >> 3;                 // 0..31 (W row)
    int jq = (tid & 7) << 2;           // 0..28 (W col quad)
#pragma unroll
    for (int p = 0; p < 4; p++) {
        const float4 w = *(const float4*)(W + ((size_t)((e * 4 + p) * 512 + ti * 32 + ii) * 512 + tj * 32 + jq));
        Ws[p][jq + 0][ii] = w.x;
        Ws[p][jq + 1][ii] = w.y;
        Ws[p][jq + 2][ii] = w.z;
        Ws[p][jq + 3][ii] = w.w;
    }
    __syncthreads();
    int jj = tid >> 3;                 // output row within tile (o)
    int iq = (tid & 7) << 2;           // output col quad (d)
    float w0 = Ws[0][jj][iq], w0b = Ws[0][jj][iq+1], w0c = Ws[0][jj][iq+2], w0d = Ws[0][jj][iq+3];
    float w1 = Ws[1][jj][iq], w1b = Ws[1][jj][iq+1], w1c = Ws[1][jj][iq+2], w1d = Ws[1][jj][iq+3];
    float w2 = Ws[2][jj][iq], w2b = Ws[2][jj][iq+1], w2c = Ws[2][jj][iq+2], w2d = Ws[2][jj][iq+3];
    float w3 = Ws[3][jj][iq], w3b = Ws[3][jj][iq+1], w3c = Ws[3][jj][iq+2], w3d = Ws[3][jj][iq+3];
#pragma unroll
    for (int a = 0; a < 4; a++) {
#pragma unroll
        for (int b = 0; b < 4; b++) {
            float r0 = rule[((e * 4 + 0) * 4 + a) * 4 + b];
            float r1 = rule[((e * 4 + 1) * 4 + a) * 4 + b];
            float r2 = rule[((e * 4 + 2) * 4 + a) * 4 + b];
            float r3 = rule[((e * 4 + 3) * 4 + a) * 4 + b];
            float o0 = r0 * w0  + r1 * w1  + r2 * w2  + r3 * w3;
            float o1 = r0 * w0b + r1 * w1b + r2 * w2b + r3 * w3b;
            float o2 = r0 * w0c + r1 * w1c + r2 * w2c + r3 * w3c;
            float o3 = r0 * w0d + r1 * w1d + r2 * w2d + r3 * w3d;
            __half2 h0 = __float22half2_rn(make_float2(o0, o1));
            __half2 h1 = __float22half2_rn(make_float2(o2, o3));
            __half* dst = g_WfullT + ((size_t)e * ODIM + b * 512 + tj * 32 + jj) * DIM
                        + a * 512 + ti * 32 + iq;
            *(__half2*)(dst)     = h0;
            *(__half2*)(dst + 2) = h1;
        }
    }
}

// ---------------- HMMA fp16 grouped GEMM: 128x256 tiles, warp tile 64x64 ----------------
__global__ __launch_bounds__(256, 1) void gemm_k(const float* __restrict__ bias,
                                                 float* __restrict__ out) {
    extern __shared__ char smem[];
    int tile = blockIdx.x;
    if (tile >= g_numtiles) return;

    int*   sTok = (int*)smem;            // 128 ints
    float* sPr  = (float*)(smem + 512);  // 128 floats
    uint32_t sbu = smem_u32(smem);

    int e = g_tile_e[tile], r0 = g_tile_r0[tile], nv = g_tile_nv[tile];
    int colBase = blockIdx.y * BN;
    int tid = threadIdx.x, wid = tid >> 5, lane = tid & 31;
    int warp_m = wid >> 2, warp_n = wid & 3;

    if (tid < BM) {
        int t = g_perm[r0 + tid];
        sTok[tid] = t;
        sPr[tid]  = g_tprob[t];
    }
    __syncthreads();

    const __half* Abase = g_Xperm  + (size_t)r0 * DIM;
    const __half* Bbase = g_WfullT + ((size_t)e * ODIM + colBase) * DIM;

    auto load_chunk = [&](int c) {
        int s = c % 3;
        uint32_t sa = sbu + 1024 + s * STAGE_BYTES;
        uint32_t sb = sa + BM * 128;
        const __half* ga = Abase + c * BK;
        const __half* gb = Bbase + c * BK;
#pragma unroll
        for (int i = 0; i < 4; i++) {                 // A: 1024 16B units
            int u = tid + i * 256;
            int row = u >> 3, sub = u & 7;
            CP_ASYNC16(sa + SW128(row * 128 + sub * 16), ga + (size_t)row * DIM + sub * 8);
        }
#pragma unroll
        for (int i = 0; i < 8; i++) {                 // B: 2048 16B units
            int u = tid + i * 256;
            int row = u >> 3, sub = u & 7;
            CP_ASYNC16(sb + SW128(row * 128 + sub * 16), gb + (size_t)row * DIM + sub * 8);
        }
    };

    float acc[4][8][4];
#pragma unroll
    for (int i = 0; i < 4; i++)
#pragma unroll
        for (int j = 0; j < 8; j++)
#pragma unroll
            for (int k = 0; k < 4; k++) acc[i][j][k] = 0.f;

    int q = lane >> 3, r = lane & 7;
    int mA  = warp_m * 64 + r + ((q & 1) << 3);
    int kqa = (q >> 1) << 4;
    int nB  = warp_n * 64 + r + ((q >> 1) << 3);
    int kqb = (q & 1) << 4;

    load_chunk(0); CP_COMMIT();
    load_chunk(1); CP_COMMIT();

    for (int c = 0; c < NC; c++) {
        CP_WAIT1();
        __syncthreads();
        if (c + 2 < NC) load_chunk(c + 2);
        CP_COMMIT();

        uint32_t sa = sbu + 1024 + (c % 3) * STAGE_BYTES;
        uint32_t sb = sa + BM * 128;
#pragma unroll
        for (int step = 0; step < 4; step++) {
            uint32_t a[4][4];
#pragma unroll
            for (int mt = 0; mt < 4; mt++)
                ldsm_x4(a[mt], sa + SW128((mA + mt * 16) * 128 + step * 32 + kqa));
            uint32_t bf[4][4];
#pragma unroll
            for (int np = 0; np < 4; np++)
                ldsm_x4(bf[np], sb + SW128((nB + np * 16) * 128 + step * 32 + kqb));
#pragma unroll
            for (int mt = 0; mt < 4; mt++)
#pragma unroll
                for (int nt = 0; nt < 8; nt++)
                    mma16816(acc[mt][nt], a[mt],
                             bf[nt >> 1][(nt & 1) << 1], bf[nt >> 1][((nt & 1) << 1) + 1]);
        }
    }

    // epilogue: scatter rows, add bias, scale by gate prob
    int rowq = lane >> 2, colq = (lane & 3) << 1;
    const float* bp = bias + e * ODIM + colBase;
#pragma unroll
    for (int mt = 0; mt < 4; mt++) {
#pragma unroll
        for (int half = 0; half < 2; half++) {
            int rl = warp_m * 64 + mt * 16 + rowq + half * 8;
            if (rl < nv) {
                int t = sTok[rl];
                float pr = sPr[rl];
                float* op = out + (size_t)t * ODIM + colBase;
#pragma unroll
                for (int nt = 0; nt < 8; nt++) {
                    int col = warp_n * 64 + nt * 8 + colq;
                    float2 b2 = *(const float2*)(bp + col);
                    float2 o;
                    o.x = (acc[mt][nt][half * 2 + 0] + b2.x) * pr;
                    o.y = (acc[mt][nt][half * 2 + 1] + b2.y) * pr;
                    *(float2*)(op + col) = o;
                }
            }
        }
    }
}

extern "C" void kernel_launch(void* const* d_in, const int* in_sizes, int n_in,
                              void* d_out, int out_size) {
    const float* x    = (const float*)d_in[0];
    const float* gw   = (const float*)d_in[1];
    const float* rule = (const float*)d_in[2];
    const float* W    = (const float*)d_in[3];
    const float* bias = (const float*)d_in[4];
    float* out = (float*)d_out;

    cudaFuncSetAttribute(gemm_k, cudaFuncAttributeMaxDynamicSharedMemorySize, SMEM_SZ);

    zero_k<<<1, 32>>>();
    gate_k<<<1024, 256>>>(x, gw);
    prep_scatter_k<<<1, 256>>>(out);
    permute_k<<<T_TOK, 256>>>(x);
    wfullT_k<<<2048, 256>>>(rule, W);
    dim3 grid(72, ODIM / BN);
    gemm_k<<<grid, 256, SMEM_SZ>>>(bias, out);
}